// round 3
// baseline (speedup 1.0000x reference)
#include <cuda_runtime.h>
#include <cstdint>
#include <cstddef>

#define NS   730
#define NG   1000
#define MUc  8
#define NCH  (NG*MUc)
#define BATCH 8
#define PRECSf 1e-05f

__constant__ float LBc[13] = {1.0f, 50.0f, 0.05f, 0.01f, 0.001f, 0.2f, 0.0f, 0.0f, -2.5f, 0.5f, 0.0f, 0.0f, 0.3f};
__constant__ float UBc[13] = {6.0f, 1000.0f, 0.9f, 0.5f, 0.2f, 1.0f, 10.0f, 100.0f, 2.5f, 10.0f, 0.1f, 0.2f, 5.0f};

// Guaranteed MUFU ops regardless of nvcc fast-math flags.
__device__ __forceinline__ float fast_lg2(float a) {
    float r; asm("lg2.approx.f32 %0, %1;" : "=f"(r) : "f"(a)); return r;
}
__device__ __forceinline__ float fast_ex2(float a) {
    float r; asm("ex2.approx.f32 %0, %1;" : "=f"(r) : "f"(a)); return r;
}

// MODE=1: CI0/CI1 are the compile-time time-varying parameter slots.
// MODE=0: generic fallback, runtime i0/i1 selection.
template<int MODE, int CI0, int CI1>
__device__ __forceinline__ void run_chain(
    const float* __restrict__ x, const float* __restrict__ par,
    float* __restrict__ out, int g, int m, int staind, int i0, int i1)
{
    // ---- constant parameters from the staind row, pre-transformed ----
    float cp[13];
    {
        const float* pb = par + ((size_t)staind*NG + (size_t)g)*13u*MUc + m;
        #pragma unroll
        for (int p = 0; p < 13; p++)
            cp[p] = fmaf(pb[(size_t)p*MUc], (UBc[p]-LBc[p]), LBc[p]);
    }
    const float lb0 = LBc[i0], d0 = UBc[i0]-LBc[i0];
    const float lb1 = LBc[i1], d1 = UBc[i1]-LBc[i1];

    const float* xp  = x   + (size_t)g*3;
    const float* pp0 = par + ((size_t)g*13 + (size_t)i0)*MUc + m;
    const float* pp1 = par + ((size_t)g*13 + (size_t)i1)*MUc + m;
    const long XS = (long)NG*3;          // x elements per timestep
    const long PS = (long)NG*13*MUc;     // param elements per timestep

    float SP=0.001f, MW=0.001f, SM=0.001f, SUZ=0.001f, SLZ=0.001f;

    auto step = [&](float P_, float T_, float E_, float raw0, float raw1) -> float {
        float v0 = fmaf(raw0, d0, lb0);
        float v1 = fmaf(raw1, d1, lb1);
        #define GP(P) (MODE ? (((P)==CI0) ? v0 : (((P)==CI1) ? v1 : cp[(P)])) \
                            : (((P)==i1) ? v1 : (((P)==i0) ? v0 : cp[(P)])))
        float BETA=GP(0), FC=GP(1), K0=GP(2), K1=GP(3), K2=GP(4), LP=GP(5),
              PERCc=GP(6), UZL=GP(7), TT=GP(8), CFMAX=GP(9), CFR=GP(10),
              CWH=GP(11), BETAET=GP(12);
        #undef GP
        // ---- snow module (off critical path) ----
        float rain = (T_ >= TT) ? P_ : 0.0f;
        float snow = P_ - rain;
        SP += snow;
        float melt = fminf(fmaxf(CFMAX*(T_-TT), 0.0f), SP);
        MW += melt; SP -= melt;
        float refr = fminf(fmaxf(CFR*CFMAX*(TT-T_), 0.0f), MW);
        SP += refr; MW -= refr;
        float tosoil = fmaxf(MW - CWH*SP, 0.0f);
        MW -= tosoil;
        // ---- soil module (loop-carried critical chain: 2x lg2/ex2) ----
        float lgFC   = fast_lg2(FC);       // hoisted by ptxas in MODE=1 (FC const per chain)
        float lgLPFC = fast_lg2(LP*FC);    // hoisted in MODE=1
        float sw = fast_ex2(BETA*(fast_lg2(SM) - lgFC));
        sw = fminf(sw, 1.0f);
        float rt = rain + tosoil;
        float recharge = rt * sw;
        float SM1 = SM + rt - recharge;
        float excess = fmaxf(SM1 - FC, 0.0f);
        float SM2 = SM1 - excess;
        float ef = fast_ex2(BETAET*(fast_lg2(SM2) - lgLPFC));
        ef = fminf(ef, 1.0f);
        float ETact = fminf(SM2, E_*ef);
        SM = fmaxf(SM2 - ETact, PRECSf);
        // ---- routing ----
        SUZ += recharge + excess;
        float PERC = fminf(SUZ, PERCc);
        SUZ -= PERC;
        float Q0 = K0 * fmaxf(SUZ - UZL, 0.0f);
        SUZ -= Q0;
        float Q1 = K1 * SUZ;
        SUZ -= Q1;
        SLZ += PERC;
        float Q2 = K2 * SLZ;
        SLZ -= Q2;
        return Q0 + Q1 + Q2;
    };

    // ---- software-pipelined main loop, 8-step batches ----
    float cP[BATCH], cT[BATCH], cE[BATCH], c0[BATCH], c1[BATCH];
    #pragma unroll
    for (int j = 0; j < BATCH; j++) {
        cP[j] = xp[(long)j*XS + 0];
        cT[j] = xp[(long)j*XS + 1];
        cE[j] = xp[(long)j*XS + 2];
        c0[j] = pp0[(long)j*PS];
        c1[j] = pp1[(long)j*PS];
    }
    const float invmu = 1.0f/(float)MUc;
    const unsigned FULL = 0xffffffffu;
    const int NB = NS/BATCH;          // 91 full batches (728 steps), tail = 2
    const bool hi4 = (m & 4) != 0, hi2 = (m & 2) != 0, hi1 = (m & 1) != 0;

    for (int b = 0; b < NB; b++) {
        // prefetch next batch (predicated near the end; never dereferenced OOB)
        int tn = (b+1)*BATCH;
        float nP[BATCH], nT[BATCH], nE[BATCH], n0[BATCH], n1[BATCH];
        const float* xq = xp  + (long)tn*XS;
        const float* q0 = pp0 + (long)tn*PS;
        const float* q1 = pp1 + (long)tn*PS;
        #pragma unroll
        for (int j = 0; j < BATCH; j++) {
            bool ok = (tn + j) < NS;
            nP[j] = ok ? xq[(long)j*XS + 0] : 0.0f;
            nT[j] = ok ? xq[(long)j*XS + 1] : 0.0f;
            nE[j] = ok ? xq[(long)j*XS + 2] : 0.0f;
            n0[j] = ok ? q0[(long)j*PS] : 0.0f;
            n1[j] = ok ? q1[(long)j*PS] : 0.0f;
        }
        // compute 8 steps
        float q[BATCH];
        #pragma unroll
        for (int j = 0; j < BATCH; j++)
            q[j] = step(cP[j], cT[j], cE[j], c0[j], c1[j]);
        // recursive-halving reduce-scatter over the 8-lane mu group:
        // lane m ends up owning the group total for step (b*8 + m).
        float s1[4];
        #pragma unroll
        for (int e = 0; e < 4; e++) {
            float send = hi4 ? q[e] : q[e+4];
            float recv = __shfl_xor_sync(FULL, send, 4);
            s1[e] = (hi4 ? q[e+4] : q[e]) + recv;
        }
        float s2[2];
        #pragma unroll
        for (int e = 0; e < 2; e++) {
            float send = hi2 ? s1[e] : s1[e+2];
            float recv = __shfl_xor_sync(FULL, send, 2);
            s2[e] = (hi2 ? s1[e+2] : s1[e]) + recv;
        }
        {
            float send = hi1 ? s2[0] : s2[1];
            float recv = __shfl_xor_sync(FULL, send, 1);
            float tot  = (hi1 ? s2[1] : s2[0]) + recv;
            out[(size_t)(b*BATCH + m)*NG + g] = tot * invmu;
        }
        #pragma unroll
        for (int j = 0; j < BATCH; j++) {
            cP[j]=nP[j]; cT[j]=nT[j]; cE[j]=nE[j]; c0[j]=n0[j]; c1[j]=n1[j];
        }
    }
    // ---- tail (steps 728, 729): data already in c* from last prefetch ----
    #pragma unroll
    for (int t = NB*BATCH; t < NS; t++) {
        int j = t - NB*BATCH;
        float qv = step(cP[j], cT[j], cE[j], c0[j], c1[j]);
        qv += __shfl_xor_sync(FULL, qv, 1);
        qv += __shfl_xor_sync(FULL, qv, 2);
        qv += __shfl_xor_sync(FULL, qv, 4);
        if (m == 0) out[(size_t)t*NG + g] = qv * invmu;
    }
}

__global__ void __launch_bounds__(64, 1)
hbv_kernel(const float* __restrict__ x, const float* __restrict__ par,
           const int* __restrict__ staind_p, const int* __restrict__ tdlst_p,
           int n_td, float* __restrict__ out)
{
    int tid = blockIdx.x * 64 + threadIdx.x;   // grid sized exactly: 8000 threads
    int g = tid >> 3;
    int m = tid & 7;
    int staind = staind_p[0];
    int t0 = tdlst_p[0];
    int t1 = (n_td > 1) ? tdlst_p[1] : t0;
    int i0 = ((t0 - 1) % 13 + 13) % 13;
    int i1 = ((t1 - 1) % 13 + 13) % 13;

    if (i0 == 12 && i1 == 0)      run_chain<1, 12, 0>(x, par, out, g, m, staind, i0, i1);
    else if (i0 == 0 && i1 == 12) run_chain<1, 0, 12>(x, par, out, g, m, staind, i0, i1);
    else                          run_chain<0, 0, 0>(x, par, out, g, m, staind, i0, i1);
}

extern "C" void kernel_launch(void* const* d_in, const int* in_sizes, int n_in,
                              void* d_out, int out_size)
{
    const float* x      = (const float*)d_in[0];   // (730, 1000, 3) f32
    const float* par    = (const float*)d_in[1];   // (730, 1000, 13, 8) f32
    const int*   staind = (const int*)d_in[2];     // scalar
    const int*   tdlst  = (const int*)d_in[3];     // (2,) int32
    int n_td = in_sizes[3];
    (void)n_in; (void)out_size;
    hbv_kernel<<<NCH/64, 64>>>(x, par, staind, tdlst, n_td, (float*)d_out);
}